// round 16
// baseline (speedup 1.0000x reference)
#include <cuda_runtime.h>
#include <cuda_fp16.h>
#include <math.h>

// Fixed problem shapes
constexpr int B  = 8;
constexpr int H  = 384;
constexpr int W  = 512;
constexpr int HW = H * W;            // 196608
constexpr int NPIX = B * HW;         // 1572864
constexpr int N3 = B * 3 * HW;

constexpr int TPB = 256;
constexpr int NQUAD = NPIX / 4;
constexpr int NBLKQ = NQUAD / TPB;          // 1536
constexpr int NPAIR = NPIX / 2;
constexpr int NBLKP = NPAIR / TPB;          // 3072
constexpr int NOCT  = NPIX / 8;             // 196608 (4x2 tiles)
constexpr int NBLKO = NOCT / TPB;           // 768
constexpr unsigned GRAD_BLOCKS = NBLKO * 2; // 1536

// 5-tap gradient filter coefficients (center tap is 0)
constexpr float KC0 = -1.0f / 12.0f;
constexpr float KC1 =  2.0f / 3.0f;
constexpr float KC3 = -2.0f / 3.0f;
constexpr float KC4 =  1.0f / 12.0f;

// Scratch (static device globals; zero-initialized at module load)
__device__ __half2 g_flow[2][NPIX];    // interleaved (fx,fy) fp16 per pixel
__device__ __half  g_res [2][N3];      // fp16 warp residual per direction
__device__ __half  g_mask[2][NPIX];    // fp16 border*occ mask per direction
__device__ float   g_acc [3];          // [0]=energy, [1]=logvar raw, [2]=epe
__device__ unsigned g_done;            // last-block counter

__device__ __forceinline__ float sigm(float x) {
    return 1.0f / (1.0f + __expf(-x));
}
__device__ __forceinline__ float4 ld4(const float* p) {
    return *reinterpret_cast<const float4*>(p);
}
__device__ __forceinline__ float2 ld2(const float* p) {
    return *reinterpret_cast<const float2*>(p);
}
__device__ __forceinline__ void unpack(float4 v, float* a) {
    a[0] = v.x; a[1] = v.y; a[2] = v.z; a[3] = v.w;
}
// 4 halfs <-> 4 floats, single 8B transaction
__device__ __forceinline__ void st_h4(__half* p, const float* a) {
    __half2 h0 = __floats2half2_rn(a[0], a[1]);
    __half2 h1 = __floats2half2_rn(a[2], a[3]);
    uint2 u;
    u.x = *reinterpret_cast<unsigned*>(&h0);
    u.y = *reinterpret_cast<unsigned*>(&h1);
    *reinterpret_cast<uint2*>(p) = u;
}
__device__ __forceinline__ void ld_h4(const __half* p, float* a) {
    uint2 u = *reinterpret_cast<const uint2*>(p);
    __half2 h0 = *reinterpret_cast<__half2*>(&u.x);
    __half2 h1 = *reinterpret_cast<__half2*>(&u.y);
    float2 f0 = __half22float2(h0);
    float2 f1 = __half22float2(h1);
    a[0] = f0.x; a[1] = f0.y; a[2] = f1.x; a[3] = f1.y;
}
// Load 4 interleaved flow pixels (16B) into fx[4], fy[4]
__device__ __forceinline__ void ld_flow4(const __half2* p, float* fx, float* fy) {
    uint4 u = *reinterpret_cast<const uint4*>(p);
    const __half2* h = reinterpret_cast<const __half2*>(&u);
    #pragma unroll
    for (int i = 0; i < 4; ++i) {
        float2 f = __half22float2(h[i]);
        fx[i] = f.x; fy[i] = f.y;
    }
}

__device__ __forceinline__ float blockReduceSum(float v) {
    __shared__ float s[32];
    int lane = threadIdx.x & 31;
    int wid  = threadIdx.x >> 5;
    #pragma unroll
    for (int o = 16; o; o >>= 1) v += __shfl_down_sync(0xffffffffu, v, o);
    if (lane == 0) s[wid] = v;
    __syncthreads();
    v = 0.0f;
    if (wid == 0) {
        v = (lane < (TPB >> 5)) ? s[lane] : 0.0f;
        #pragma unroll
        for (int o = 16; o; o >>= 1) v += __shfl_down_sync(0xffffffffu, v, o);
    }
    return v;
}

// Reparameterize flows into interleaved fp16x2; entropy raw-sum + EPE sum.
// 2 pixels/thread, high occupancy for max memory-level parallelism.
__global__ void __launch_bounds__(TPB, 7) k_flow(
    const float* __restrict__ mf, const float* __restrict__ lvf,
    const float* __restrict__ mb, const float* __restrict__ lvb,
    const float* __restrict__ tgt,
    const float* __restrict__ nf, const float* __restrict__ nb)
{
    int idx = blockIdx.x * blockDim.x + threadIdx.x;  // [0, NPAIR)
    int p = idx * 2;
    int b  = p / HW;
    int rr = p - b * HW;
    int i0 = (b * 2) * HW + rr;
    int i1 = i0 + HW;

    // Channel-0 loads
    float2 a0f = ld2(mf  + i0), l0f = ld2(lvf + i0), n0f = ld2(nf + i0);
    float2 a0b = ld2(mb  + i0), l0b = ld2(lvb + i0), n0b = ld2(nb + i0);
    float2 t0  = ld2(tgt + i0);
    // Channel-1 loads
    float2 a1f = ld2(mf  + i1), l1f = ld2(lvf + i1), n1f = ld2(nf + i1);
    float2 a1b = ld2(mb  + i1), l1b = ld2(lvb + i1), n1b = ld2(nb + i1);
    float2 t1  = ld2(tgt + i1);

    float ffx0 = a0f.x + __expf(l0f.x * 0.5f) * n0f.x;
    float ffx1 = a0f.y + __expf(l0f.y * 0.5f) * n0f.y;
    float ffy0 = a1f.x + __expf(l1f.x * 0.5f) * n1f.x;
    float ffy1 = a1f.y + __expf(l1f.y * 0.5f) * n1f.y;
    float fbx0 = a0b.x + __expf(l0b.x * 0.5f) * n0b.x;
    float fbx1 = a0b.y + __expf(l0b.y * 0.5f) * n0b.y;
    float fby0 = a1b.x + __expf(l1b.x * 0.5f) * n1b.x;
    float fby1 = a1b.y + __expf(l1b.y * 0.5f) * n1b.y;

    float ent = l0f.x + l0f.y + l1f.x + l1f.y
              + l0b.x + l0b.y + l1b.x + l1b.y;

    float dx0 = a0f.x - t0.x, dy0 = a1f.x - t1.x;
    float dx1 = a0f.y - t0.y, dy1 = a1f.y - t1.y;
    float epe = sqrtf(dx0 * dx0 + dy0 * dy0) + sqrtf(dx1 * dx1 + dy1 * dy1);

    {
        __half2 hf[2] = { __floats2half2_rn(ffx0, ffy0), __floats2half2_rn(ffx1, ffy1) };
        *reinterpret_cast<uint2*>(&g_flow[0][b * HW + rr]) = *reinterpret_cast<uint2*>(hf);
        __half2 hb[2] = { __floats2half2_rn(fbx0, fby0), __floats2half2_rn(fbx1, fby1) };
        *reinterpret_cast<uint2*>(&g_flow[1][b * HW + rr]) = *reinterpret_cast<uint2*>(hb);
    }

    float es = blockReduceSum(ent);
    __syncthreads();
    float ps = blockReduceSum(epe);
    if (threadIdx.x == 0) {
        atomicAdd(&g_acc[1], es);
        atomicAdd(&g_acc[2], ps);
    }
}

// Per-direction main energy (both directions via blockIdx.y), 4 pixels/thread.
// Interior fast path: no clamp/valid logic when all 4 taps are in-bounds.
__global__ void __launch_bounds__(TPB) k_dir(
    const float* __restrict__ img1, const float* __restrict__ img2)
{
    int dir = blockIdx.y;
    const float* __restrict__ imgA = dir ? img2 : img1;
    const float* __restrict__ imgB = dir ? img1 : img2;

    int q = blockIdx.x * blockDim.x + threadIdx.x;
    int p = q * 4;
    int b  = p / HW;
    int rr = p - b * HW;
    int y  = rr / W;
    int x  = rr - y * W;

    const __half2* __restrict__ fA = g_flow[dir]     + b * HW;
    const __half2* __restrict__ fB = g_flow[dir ^ 1] + b * HW;
    __half* __restrict__ res  = g_res[dir];
    __half* __restrict__ mout = g_mask[dir];

    int baseI = (b * 3) * HW;

    float fax[4], fay[4];
    ld_flow4(fA + rr, fax, fay);

    float ia[3][4];
    #pragma unroll
    for (int c = 0; c < 3; ++c) unpack(ld4(imgA + baseI + c * HW + rr), ia[c]);

    const float* ib0 = imgB + baseI;
    const float* ib1 = ib0 + HW;
    const float* ib2 = ib1 + HW;

    float maskv[4];
    float rc[3][4];
    float e = 0.0f;

    #pragma unroll
    for (int i = 0; i < 4; ++i) {
        float Xp = (float)(x + i) + fax[i];
        float Yp = (float)y + fay[i];

        float mx = sigm(Xp + 0.5f) * (1.0f - sigm(Xp - ((float)W - 0.5f)));
        float my = sigm(Yp + 0.5f) * (1.0f - sigm(Yp - ((float)H - 0.5f)));
        float border = mx * my;

        float x0f = floorf(Xp), y0f = floorf(Yp);
        float wx = Xp - x0f,    wy = Yp - y0f;
        int x0 = (int)x0f, y0 = (int)y0f;

        float w00, w10, w01, w11;
        int i00, i10, i01, i11;
        if (Xp >= 0.0f && Xp < (float)(W - 1) && Yp >= 0.0f && Yp < (float)(H - 1)) {
            // Interior: all 4 taps valid, no clamping needed.
            w00 = (1.0f - wx) * (1.0f - wy);
            w10 = wx * (1.0f - wy);
            w01 = (1.0f - wx) * wy;
            w11 = wx * wy;
            i00 = y0 * W + x0;
            i10 = i00 + 1;
            i01 = i00 + W;
            i11 = i01 + 1;
        } else {
            bool vx0 = (x0 >= 0)     && (x0 <= W - 1);
            bool vx1 = (x0 + 1 >= 0) && (x0 + 1 <= W - 1);
            bool vy0 = (y0 >= 0)     && (y0 <= H - 1);
            bool vy1 = (y0 + 1 >= 0) && (y0 + 1 <= H - 1);
            w00 = (1.0f - wx) * (1.0f - wy) * (float)(vx0 && vy0);
            w10 = wx * (1.0f - wy)          * (float)(vx1 && vy0);
            w01 = (1.0f - wx) * wy          * (float)(vx0 && vy1);
            w11 = wx * wy                    * (float)(vx1 && vy1);
            int cx0 = min(max(x0, 0), W - 1);
            int cx1 = min(max(x0 + 1, 0), W - 1);
            int cy0 = min(max(y0, 0), H - 1);
            int cy1 = min(max(y0 + 1, 0), H - 1);
            i00 = cy0 * W + cx0;
            i10 = cy0 * W + cx1;
            i01 = cy1 * W + cx0;
            i11 = cy1 * W + cx1;
        }

        // Interleaved fp16x2 flow gather: 4 loads give both channels
        float2 f00 = __half22float2(fB[i00]);
        float2 f10 = __half22float2(fB[i10]);
        float2 f01 = __half22float2(fB[i01]);
        float2 f11 = __half22float2(fB[i11]);
        float fbw0 = w00 * f00.x + w10 * f10.x + w01 * f01.x + w11 * f11.x;
        float fbw1 = w00 * f00.y + w10 * f10.y + w01 * f01.y + w11 * f11.y;

        float mag = fax[i] * fax[i] + fay[i] * fay[i] + fbw0 * fbw0 + fbw1 * fbw1;
        float dfx = fax[i] + fbw0;
        float dfy = fay[i] + fbw1;
        float D   = dfx * dfx + dfy * dfy;
        float occ = 1.0f - sigm(D - (0.01f * mag + 0.5f));
        float mask = border * occ;
        maskv[i] = mask;

        float w0 = w00 * ib0[i00] + w10 * ib0[i10] + w01 * ib0[i01] + w11 * ib0[i11];
        float w1 = w00 * ib1[i00] + w10 * ib1[i10] + w01 * ib1[i01] + w11 * ib1[i11];
        float w2 = w00 * ib2[i00] + w10 * ib2[i10] + w01 * ib2[i01] + w11 * ib2[i11];
        rc[0][i] = ia[0][i] - w0;
        rc[1][i] = ia[1][i] - w1;
        rc[2][i] = ia[2][i] - w2;
        float A = rc[0][i] * rc[0][i] + rc[1][i] * rc[1][i] + rc[2][i] * rc[2][i];

        // Inline energy: mask + data + fb terms
        e += (1.0f - mask)
           + sqrtf(A + 1e-5f) * mask
           + sqrtf(D + 1e-5f) * mask;
    }

    st_h4(&mout[p], maskv);
    #pragma unroll
    for (int c = 0; c < 3; ++c)
        st_h4(&res[baseI + c * HW + rr], rc[c]);

    // Smoothness
    bool hasR = (x + 4) < W;
    float faxn = 0.0f, fayn = 0.0f;
    if (hasR) {
        float2 fn = __half22float2(fA[rr + 4]);
        faxn = fn.x; fayn = fn.y;
    }
    bool hasD = (y + 1) < H;
    float faxd[4] = {0, 0, 0, 0}, fayd[4] = {0, 0, 0, 0};
    if (hasD) ld_flow4(fA + rr + W, faxd, fayd);

    #pragma unroll
    for (int i = 0; i < 4; ++i) {
        float dx2 = 0.0f;
        if (x + i < W - 1) {
            float nx = (i < 3) ? fax[i + 1] : faxn;
            float ny = (i < 3) ? fay[i + 1] : fayn;
            float d0 = nx - fax[i];
            float d1 = ny - fay[i];
            dx2 = d0 * d0 + d1 * d1;
        }
        float dy2 = 0.0f;
        if (hasD) {
            float d0 = faxd[i] - fax[i];
            float d1 = fayd[i] - fay[i];
            dy2 = d0 * d0 + d1 * d1;
        }
        e += sqrtf(dx2 + dy2 + 1e-5f);
    }

    float bs = blockReduceSum(e);
    if (threadIdx.x == 0) atomicAdd(&g_acc[0], bs);
}

// Gradient-constancy term on fp16 residuals, 4x2-pixel tile per thread,
// plus last-block final output.
__global__ void __launch_bounds__(TPB) k_grad(float* __restrict__ out)
{
    int dir = blockIdx.y;
    int qid = blockIdx.x * blockDim.x + threadIdx.x;   // [0, NOCT)
    int qx = qid & 127;                  // 128 quads per row
    int rp = qid >> 7;                   // row-pair index
    int b  = rp / (H / 2);
    int y  = 2 * (rp - b * (H / 2));     // even row in [0, H-2]
    int x  = qx * 4;
    int rr = y * W + x;

    const __half* __restrict__ res = g_res[dir];
    int baseI = (b * 3) * HW;

    bool hasL = x >= 4;
    bool hasR = (x + 4) < W;
    bool hYm2 = y >= 2, hYm1 = y >= 1;
    bool hYp2 = (y + 2) < H, hYp3 = (y + 3) < H;

    float Ct0[4] = {0, 0, 0, 0};
    float Ct1[4] = {0, 0, 0, 0};

    #pragma unroll
    for (int c = 0; c < 3; ++c) {
        const __half* rb = res + baseI + c * HW + rr;

        float a0[12], a1[12];
        if (hasL) { ld_h4(rb - 4, &a0[0]); ld_h4(rb + W - 4, &a1[0]); }
        else { a0[0]=a0[1]=a0[2]=a0[3]=0.0f; a1[0]=a1[1]=a1[2]=a1[3]=0.0f; }
        ld_h4(rb,     &a0[4]);
        ld_h4(rb + W, &a1[4]);
        if (hasR) { ld_h4(rb + 4, &a0[8]); ld_h4(rb + W + 4, &a1[8]); }
        else { a0[8]=a0[9]=a0[10]=a0[11]=0.0f; a1[8]=a1[9]=a1[10]=a1[11]=0.0f; }

        float rm2[4] = {0,0,0,0}, rm1[4] = {0,0,0,0}, rp2[4] = {0,0,0,0}, rp3[4] = {0,0,0,0};
        if (hYm2) ld_h4(rb - 2 * W, rm2);
        if (hYm1) ld_h4(rb - W, rm1);
        if (hYp2) ld_h4(rb + 2 * W, rp2);
        if (hYp3) ld_h4(rb + 3 * W, rp3);

        #pragma unroll
        for (int i = 0; i < 4; ++i) {
            float gx0 = KC0 * a0[i + 2] + KC1 * a0[i + 3] + KC3 * a0[i + 5] + KC4 * a0[i + 6];
            float gy0 = KC0 * rm2[i] + KC1 * rm1[i] + KC3 * a1[i + 4] + KC4 * rp2[i];
            Ct0[i] += gx0 * gx0 + gy0 * gy0;
            float gx1 = KC0 * a1[i + 2] + KC1 * a1[i + 3] + KC3 * a1[i + 5] + KC4 * a1[i + 6];
            float gy1 = KC0 * rm1[i] + KC1 * a0[i + 4] + KC3 * rp2[i] + KC4 * rp3[i];
            Ct1[i] += gx1 * gx1 + gy1 * gy1;
        }
    }

    int pm = b * HW + rr;
    float m0[4], m1[4];
    ld_h4(&g_mask[dir][pm], m0);
    ld_h4(&g_mask[dir][pm + W], m1);

    float e = 0.0f;
    #pragma unroll
    for (int i = 0; i < 4; ++i) {
        e += sqrtf(Ct0[i] + 1e-5f) * m0[i];
        e += sqrtf(Ct1[i] + 1e-5f) * m1[i];
    }

    float bs = blockReduceSum(e);

    // Last-block epilogue
    if (threadIdx.x == 0) {
        atomicAdd(&g_acc[0], bs);
        __threadfence();
        unsigned n = atomicAdd(&g_done, 1u);
        if (n == GRAD_BLOCKS - 1) {
            __threadfence();
            float energy  = g_acc[0] * (1.0f / (float)B);
            float entropy = g_acc[1] * (1.0f / (2.0f * (float)B));
            out[0] = energy - entropy;
            out[1] = g_acc[2] * (1.0f / (float)NPIX);
            g_acc[0] = 0.0f;
            g_acc[1] = 0.0f;
            g_acc[2] = 0.0f;
            g_done = 0u;
        }
    }
}

extern "C" void kernel_launch(void* const* d_in, const int* in_sizes, int n_in,
                              void* d_out, int out_size)
{
    const float* meanf   = (const float*)d_in[0];
    const float* logvarf = (const float*)d_in[1];
    const float* meanb   = (const float*)d_in[2];
    const float* logvarb = (const float*)d_in[3];
    const float* img1    = (const float*)d_in[4];
    const float* img2    = (const float*)d_in[5];
    const float* target  = (const float*)d_in[6];
    const float* noise_f = (const float*)d_in[7];
    const float* noise_b = (const float*)d_in[8];
    float* out = (float*)d_out;

    dim3 gridD(NBLKQ, 2);
    dim3 gridG(NBLKO, 2);

    k_flow<<<NBLKP, TPB>>>(meanf, logvarf, meanb, logvarb, target, noise_f, noise_b);
    k_dir<<<gridD, TPB>>>(img1, img2);
    k_grad<<<gridG, TPB>>>(out);
}

// round 17
// speedup vs baseline: 1.0032x; 1.0032x over previous
#include <cuda_runtime.h>
#include <cuda_fp16.h>
#include <math.h>

// Fixed problem shapes
constexpr int B  = 8;
constexpr int H  = 384;
constexpr int W  = 512;
constexpr int HW = H * W;            // 196608
constexpr int NPIX = B * HW;         // 1572864
constexpr int N3 = B * 3 * HW;

constexpr int TPB = 256;
constexpr int NQUAD = NPIX / 4;
constexpr int NBLKQ = NQUAD / TPB;          // 1536
constexpr int NPAIR = NPIX / 2;
constexpr int NBLKP = NPAIR / TPB;          // 3072
constexpr int NOCT  = NPIX / 8;             // 196608 (4x2 tiles)
constexpr int NBLKO = NOCT / TPB;           // 768
constexpr unsigned GRAD_BLOCKS = NBLKO * 2; // 1536

// 5-tap gradient filter coefficients (center tap is 0)
constexpr float KC0 = -1.0f / 12.0f;
constexpr float KC1 =  2.0f / 3.0f;
constexpr float KC3 = -2.0f / 3.0f;
constexpr float KC4 =  1.0f / 12.0f;

// Scratch (static device globals; zero-initialized at module load)
__device__ __half2 g_flow[2][NPIX];    // interleaved (fx,fy) fp16 per pixel
__device__ __half  g_res [2][N3];      // fp16 warp residual per direction
__device__ __half  g_mask[2][NPIX];    // fp16 border*occ mask per direction
__device__ float   g_acc [3];          // [0]=energy, [1]=logvar raw, [2]=epe
__device__ unsigned g_done;            // last-block counter

__device__ __forceinline__ float sigm(float x) {
    return 1.0f / (1.0f + __expf(-x));
}
__device__ __forceinline__ float4 ld4(const float* p) {
    return *reinterpret_cast<const float4*>(p);
}
__device__ __forceinline__ float2 ld2(const float* p) {
    return *reinterpret_cast<const float2*>(p);
}
__device__ __forceinline__ void unpack(float4 v, float* a) {
    a[0] = v.x; a[1] = v.y; a[2] = v.z; a[3] = v.w;
}
// 4 halfs <-> 4 floats, single 8B transaction
__device__ __forceinline__ void st_h4(__half* p, const float* a) {
    __half2 h0 = __floats2half2_rn(a[0], a[1]);
    __half2 h1 = __floats2half2_rn(a[2], a[3]);
    uint2 u;
    u.x = *reinterpret_cast<unsigned*>(&h0);
    u.y = *reinterpret_cast<unsigned*>(&h1);
    *reinterpret_cast<uint2*>(p) = u;
}
__device__ __forceinline__ void ld_h4(const __half* p, float* a) {
    uint2 u = *reinterpret_cast<const uint2*>(p);
    __half2 h0 = *reinterpret_cast<__half2*>(&u.x);
    __half2 h1 = *reinterpret_cast<__half2*>(&u.y);
    float2 f0 = __half22float2(h0);
    float2 f1 = __half22float2(h1);
    a[0] = f0.x; a[1] = f0.y; a[2] = f1.x; a[3] = f1.y;
}
// Load 4 interleaved flow pixels (16B) into fx[4], fy[4]
__device__ __forceinline__ void ld_flow4(const __half2* p, float* fx, float* fy) {
    uint4 u = *reinterpret_cast<const uint4*>(p);
    const __half2* h = reinterpret_cast<const __half2*>(&u);
    #pragma unroll
    for (int i = 0; i < 4; ++i) {
        float2 f = __half22float2(h[i]);
        fx[i] = f.x; fy[i] = f.y;
    }
}

__device__ __forceinline__ float blockReduceSum(float v) {
    __shared__ float s[32];
    int lane = threadIdx.x & 31;
    int wid  = threadIdx.x >> 5;
    #pragma unroll
    for (int o = 16; o; o >>= 1) v += __shfl_down_sync(0xffffffffu, v, o);
    if (lane == 0) s[wid] = v;
    __syncthreads();
    v = 0.0f;
    if (wid == 0) {
        v = (lane < (TPB >> 5)) ? s[lane] : 0.0f;
        #pragma unroll
        for (int o = 16; o; o >>= 1) v += __shfl_down_sync(0xffffffffu, v, o);
    }
    return v;
}

// Reparameterize flows into interleaved fp16x2; entropy raw-sum + EPE sum.
// 2 pixels/thread, high occupancy for max memory-level parallelism.
__global__ void __launch_bounds__(TPB, 7) k_flow(
    const float* __restrict__ mf, const float* __restrict__ lvf,
    const float* __restrict__ mb, const float* __restrict__ lvb,
    const float* __restrict__ tgt,
    const float* __restrict__ nf, const float* __restrict__ nb)
{
    int idx = blockIdx.x * blockDim.x + threadIdx.x;  // [0, NPAIR)
    int p = idx * 2;
    int b  = p / HW;
    int rr = p - b * HW;
    int i0 = (b * 2) * HW + rr;
    int i1 = i0 + HW;

    // Channel-0 loads
    float2 a0f = ld2(mf  + i0), l0f = ld2(lvf + i0), n0f = ld2(nf + i0);
    float2 a0b = ld2(mb  + i0), l0b = ld2(lvb + i0), n0b = ld2(nb + i0);
    float2 t0  = ld2(tgt + i0);
    // Channel-1 loads
    float2 a1f = ld2(mf  + i1), l1f = ld2(lvf + i1), n1f = ld2(nf + i1);
    float2 a1b = ld2(mb  + i1), l1b = ld2(lvb + i1), n1b = ld2(nb + i1);
    float2 t1  = ld2(tgt + i1);

    float ffx0 = a0f.x + __expf(l0f.x * 0.5f) * n0f.x;
    float ffx1 = a0f.y + __expf(l0f.y * 0.5f) * n0f.y;
    float ffy0 = a1f.x + __expf(l1f.x * 0.5f) * n1f.x;
    float ffy1 = a1f.y + __expf(l1f.y * 0.5f) * n1f.y;
    float fbx0 = a0b.x + __expf(l0b.x * 0.5f) * n0b.x;
    float fbx1 = a0b.y + __expf(l0b.y * 0.5f) * n0b.y;
    float fby0 = a1b.x + __expf(l1b.x * 0.5f) * n1b.x;
    float fby1 = a1b.y + __expf(l1b.y * 0.5f) * n1b.y;

    float ent = l0f.x + l0f.y + l1f.x + l1f.y
              + l0b.x + l0b.y + l1b.x + l1b.y;

    float dx0 = a0f.x - t0.x, dy0 = a1f.x - t1.x;
    float dx1 = a0f.y - t0.y, dy1 = a1f.y - t1.y;
    float epe = sqrtf(dx0 * dx0 + dy0 * dy0) + sqrtf(dx1 * dx1 + dy1 * dy1);

    {
        __half2 hf[2] = { __floats2half2_rn(ffx0, ffy0), __floats2half2_rn(ffx1, ffy1) };
        *reinterpret_cast<uint2*>(&g_flow[0][b * HW + rr]) = *reinterpret_cast<uint2*>(hf);
        __half2 hb[2] = { __floats2half2_rn(fbx0, fby0), __floats2half2_rn(fbx1, fby1) };
        *reinterpret_cast<uint2*>(&g_flow[1][b * HW + rr]) = *reinterpret_cast<uint2*>(hb);
    }

    float es = blockReduceSum(ent);
    __syncthreads();
    float ps = blockReduceSum(epe);
    if (threadIdx.x == 0) {
        atomicAdd(&g_acc[1], es);
        atomicAdd(&g_acc[2], ps);
    }
}

// Per-direction main energy (both directions via blockIdx.y), 4 pixels/thread.
// Interior fast path: no clamp/valid logic when all 4 taps are in-bounds.
__global__ void __launch_bounds__(TPB) k_dir(
    const float* __restrict__ img1, const float* __restrict__ img2)
{
    int dir = blockIdx.y;
    const float* __restrict__ imgA = dir ? img2 : img1;
    const float* __restrict__ imgB = dir ? img1 : img2;

    int q = blockIdx.x * blockDim.x + threadIdx.x;
    int p = q * 4;
    int b  = p / HW;
    int rr = p - b * HW;
    int y  = rr / W;
    int x  = rr - y * W;

    const __half2* __restrict__ fA = g_flow[dir]     + b * HW;
    const __half2* __restrict__ fB = g_flow[dir ^ 1] + b * HW;
    __half* __restrict__ res  = g_res[dir];
    __half* __restrict__ mout = g_mask[dir];

    int baseI = (b * 3) * HW;

    float fax[4], fay[4];
    ld_flow4(fA + rr, fax, fay);

    float ia[3][4];
    #pragma unroll
    for (int c = 0; c < 3; ++c) unpack(ld4(imgA + baseI + c * HW + rr), ia[c]);

    const float* ib0 = imgB + baseI;
    const float* ib1 = ib0 + HW;
    const float* ib2 = ib1 + HW;

    float maskv[4];
    float rc[3][4];
    float e = 0.0f;

    #pragma unroll
    for (int i = 0; i < 4; ++i) {
        float Xp = (float)(x + i) + fax[i];
        float Yp = (float)y + fay[i];

        float mx = sigm(Xp + 0.5f) * (1.0f - sigm(Xp - ((float)W - 0.5f)));
        float my = sigm(Yp + 0.5f) * (1.0f - sigm(Yp - ((float)H - 0.5f)));
        float border = mx * my;

        float x0f = floorf(Xp), y0f = floorf(Yp);
        float wx = Xp - x0f,    wy = Yp - y0f;
        int x0 = (int)x0f, y0 = (int)y0f;

        float w00, w10, w01, w11;
        int i00, i10, i01, i11;
        if (Xp >= 0.0f && Xp < (float)(W - 1) && Yp >= 0.0f && Yp < (float)(H - 1)) {
            // Interior: all 4 taps valid, no clamping needed.
            w00 = (1.0f - wx) * (1.0f - wy);
            w10 = wx * (1.0f - wy);
            w01 = (1.0f - wx) * wy;
            w11 = wx * wy;
            i00 = y0 * W + x0;
            i10 = i00 + 1;
            i01 = i00 + W;
            i11 = i01 + 1;
        } else {
            bool vx0 = (x0 >= 0)     && (x0 <= W - 1);
            bool vx1 = (x0 + 1 >= 0) && (x0 + 1 <= W - 1);
            bool vy0 = (y0 >= 0)     && (y0 <= H - 1);
            bool vy1 = (y0 + 1 >= 0) && (y0 + 1 <= H - 1);
            w00 = (1.0f - wx) * (1.0f - wy) * (float)(vx0 && vy0);
            w10 = wx * (1.0f - wy)          * (float)(vx1 && vy0);
            w01 = (1.0f - wx) * wy          * (float)(vx0 && vy1);
            w11 = wx * wy                    * (float)(vx1 && vy1);
            int cx0 = min(max(x0, 0), W - 1);
            int cx1 = min(max(x0 + 1, 0), W - 1);
            int cy0 = min(max(y0, 0), H - 1);
            int cy1 = min(max(y0 + 1, 0), H - 1);
            i00 = cy0 * W + cx0;
            i10 = cy0 * W + cx1;
            i01 = cy1 * W + cx0;
            i11 = cy1 * W + cx1;
        }

        // Interleaved fp16x2 flow gather: 4 loads give both channels
        float2 f00 = __half22float2(fB[i00]);
        float2 f10 = __half22float2(fB[i10]);
        float2 f01 = __half22float2(fB[i01]);
        float2 f11 = __half22float2(fB[i11]);
        float fbw0 = w00 * f00.x + w10 * f10.x + w01 * f01.x + w11 * f11.x;
        float fbw1 = w00 * f00.y + w10 * f10.y + w01 * f01.y + w11 * f11.y;

        float mag = fax[i] * fax[i] + fay[i] * fay[i] + fbw0 * fbw0 + fbw1 * fbw1;
        float dfx = fax[i] + fbw0;
        float dfy = fay[i] + fbw1;
        float D   = dfx * dfx + dfy * dfy;
        float occ = 1.0f - sigm(D - (0.01f * mag + 0.5f));
        float mask = border * occ;
        maskv[i] = mask;

        float w0 = w00 * ib0[i00] + w10 * ib0[i10] + w01 * ib0[i01] + w11 * ib0[i11];
        float w1 = w00 * ib1[i00] + w10 * ib1[i10] + w01 * ib1[i01] + w11 * ib1[i11];
        float w2 = w00 * ib2[i00] + w10 * ib2[i10] + w01 * ib2[i01] + w11 * ib2[i11];
        rc[0][i] = ia[0][i] - w0;
        rc[1][i] = ia[1][i] - w1;
        rc[2][i] = ia[2][i] - w2;
        float A = rc[0][i] * rc[0][i] + rc[1][i] * rc[1][i] + rc[2][i] * rc[2][i];

        // Inline energy: mask + data + fb terms
        e += (1.0f - mask)
           + sqrtf(A + 1e-5f) * mask
           + sqrtf(D + 1e-5f) * mask;
    }

    st_h4(&mout[p], maskv);
    #pragma unroll
    for (int c = 0; c < 3; ++c)
        st_h4(&res[baseI + c * HW + rr], rc[c]);

    // Smoothness
    bool hasR = (x + 4) < W;
    float faxn = 0.0f, fayn = 0.0f;
    if (hasR) {
        float2 fn = __half22float2(fA[rr + 4]);
        faxn = fn.x; fayn = fn.y;
    }
    bool hasD = (y + 1) < H;
    float faxd[4] = {0, 0, 0, 0}, fayd[4] = {0, 0, 0, 0};
    if (hasD) ld_flow4(fA + rr + W, faxd, fayd);

    #pragma unroll
    for (int i = 0; i < 4; ++i) {
        float dx2 = 0.0f;
        if (x + i < W - 1) {
            float nx = (i < 3) ? fax[i + 1] : faxn;
            float ny = (i < 3) ? fay[i + 1] : fayn;
            float d0 = nx - fax[i];
            float d1 = ny - fay[i];
            dx2 = d0 * d0 + d1 * d1;
        }
        float dy2 = 0.0f;
        if (hasD) {
            float d0 = faxd[i] - fax[i];
            float d1 = fayd[i] - fay[i];
            dy2 = d0 * d0 + d1 * d1;
        }
        e += sqrtf(dx2 + dy2 + 1e-5f);
    }

    float bs = blockReduceSum(e);
    if (threadIdx.x == 0) atomicAdd(&g_acc[0], bs);
}

// Gradient-constancy term on fp16 residuals, 4x2-pixel tile per thread,
// plus last-block final output.
__global__ void __launch_bounds__(TPB) k_grad(float* __restrict__ out)
{
    int dir = blockIdx.y;
    int qid = blockIdx.x * blockDim.x + threadIdx.x;   // [0, NOCT)
    int qx = qid & 127;                  // 128 quads per row
    int rp = qid >> 7;                   // row-pair index
    int b  = rp / (H / 2);
    int y  = 2 * (rp - b * (H / 2));     // even row in [0, H-2]
    int x  = qx * 4;
    int rr = y * W + x;

    const __half* __restrict__ res = g_res[dir];
    int baseI = (b * 3) * HW;

    bool hasL = x >= 4;
    bool hasR = (x + 4) < W;
    bool hYm2 = y >= 2, hYm1 = y >= 1;
    bool hYp2 = (y + 2) < H, hYp3 = (y + 3) < H;

    float Ct0[4] = {0, 0, 0, 0};
    float Ct1[4] = {0, 0, 0, 0};

    #pragma unroll
    for (int c = 0; c < 3; ++c) {
        const __half* rb = res + baseI + c * HW + rr;

        float a0[12], a1[12];
        if (hasL) { ld_h4(rb - 4, &a0[0]); ld_h4(rb + W - 4, &a1[0]); }
        else { a0[0]=a0[1]=a0[2]=a0[3]=0.0f; a1[0]=a1[1]=a1[2]=a1[3]=0.0f; }
        ld_h4(rb,     &a0[4]);
        ld_h4(rb + W, &a1[4]);
        if (hasR) { ld_h4(rb + 4, &a0[8]); ld_h4(rb + W + 4, &a1[8]); }
        else { a0[8]=a0[9]=a0[10]=a0[11]=0.0f; a1[8]=a1[9]=a1[10]=a1[11]=0.0f; }

        float rm2[4] = {0,0,0,0}, rm1[4] = {0,0,0,0}, rp2[4] = {0,0,0,0}, rp3[4] = {0,0,0,0};
        if (hYm2) ld_h4(rb - 2 * W, rm2);
        if (hYm1) ld_h4(rb - W, rm1);
        if (hYp2) ld_h4(rb + 2 * W, rp2);
        if (hYp3) ld_h4(rb + 3 * W, rp3);

        #pragma unroll
        for (int i = 0; i < 4; ++i) {
            float gx0 = KC0 * a0[i + 2] + KC1 * a0[i + 3] + KC3 * a0[i + 5] + KC4 * a0[i + 6];
            float gy0 = KC0 * rm2[i] + KC1 * rm1[i] + KC3 * a1[i + 4] + KC4 * rp2[i];
            Ct0[i] += gx0 * gx0 + gy0 * gy0;
            float gx1 = KC0 * a1[i + 2] + KC1 * a1[i + 3] + KC3 * a1[i + 5] + KC4 * a1[i + 6];
            float gy1 = KC0 * rm1[i] + KC1 * a0[i + 4] + KC3 * rp2[i] + KC4 * rp3[i];
            Ct1[i] += gx1 * gx1 + gy1 * gy1;
        }
    }

    int pm = b * HW + rr;
    float m0[4], m1[4];
    ld_h4(&g_mask[dir][pm], m0);
    ld_h4(&g_mask[dir][pm + W], m1);

    float e = 0.0f;
    #pragma unroll
    for (int i = 0; i < 4; ++i) {
        e += sqrtf(Ct0[i] + 1e-5f) * m0[i];
        e += sqrtf(Ct1[i] + 1e-5f) * m1[i];
    }

    float bs = blockReduceSum(e);

    // Last-block epilogue
    if (threadIdx.x == 0) {
        atomicAdd(&g_acc[0], bs);
        __threadfence();
        unsigned n = atomicAdd(&g_done, 1u);
        if (n == GRAD_BLOCKS - 1) {
            __threadfence();
            float energy  = g_acc[0] * (1.0f / (float)B);
            float entropy = g_acc[1] * (1.0f / (2.0f * (float)B));
            out[0] = energy - entropy;
            out[1] = g_acc[2] * (1.0f / (float)NPIX);
            g_acc[0] = 0.0f;
            g_acc[1] = 0.0f;
            g_acc[2] = 0.0f;
            g_done = 0u;
        }
    }
}

extern "C" void kernel_launch(void* const* d_in, const int* in_sizes, int n_in,
                              void* d_out, int out_size)
{
    const float* meanf   = (const float*)d_in[0];
    const float* logvarf = (const float*)d_in[1];
    const float* meanb   = (const float*)d_in[2];
    const float* logvarb = (const float*)d_in[3];
    const float* img1    = (const float*)d_in[4];
    const float* img2    = (const float*)d_in[5];
    const float* target  = (const float*)d_in[6];
    const float* noise_f = (const float*)d_in[7];
    const float* noise_b = (const float*)d_in[8];
    float* out = (float*)d_out;

    dim3 gridD(NBLKQ, 2);
    dim3 gridG(NBLKO, 2);

    k_flow<<<NBLKP, TPB>>>(meanf, logvarf, meanb, logvarb, target, noise_f, noise_b);
    k_dir<<<gridD, TPB>>>(img1, img2);
    k_grad<<<gridG, TPB>>>(out);
}